// round 17
// baseline (speedup 1.0000x reference)
#include <cuda_runtime.h>
#include <cuda_fp16.h>
#include <cstdint>
#include <cstddef>

#define BB 256
#define TT 256
#define II 512
#define HH 1024

#define NTHREADS 256
#define NCTA 128

// ---- loop-phase dynamic smem (float offsets): triple-buffered chunks ----
#define L_A      0
#define L_A_BUF  8704                 // A chunk: 128 rows x 136 halves
#define L_W      (3*L_A_BUF)          // 26112
#define L_W_BUF  4352                 // W chunk: 64 rows x 136 halves
#define SMEM_FLOATS (L_W + 3*L_W_BUF) // 39168
#define SMEM_BYTES  (SMEM_FLOATS*4)   // 156672 B

// ---- prologue-phase aliased smem (temporally disjoint, ends 35328 < 39168) ----
#define P_A32    0
#define P_A32_BUF (256*36)            // 9216
#define P_W32    (2*P_A32_BUF)        // 18432
#define P_W32_BUF (128*36)            // 4608
#define P_A16    27648                // 256 x 40 halves
#define P_W16    (P_A16 + 5120)       // 32768: 128 x 40 halves

// ---- persistent device state ----
__device__ __half   g_h[2][BB * HH];                 // double-buffered h (fp16)
__device__ __half   g_w16ring[2][HH * HH];           // 2-step Wh fp16 ring (4MB, L2-resident)
__device__ float    g_xpart[(size_t)TT * BB * HH];   // x@Wx^T fp32, sorted rows
__device__ unsigned g_cnt[3];
__device__ unsigned g_gen[3];
__device__ unsigned g_hflag[2];                      // h writers per half (16/step)
__device__ unsigned g_wready[2];                     // helpers filled ring slot (96/fill)
__device__ unsigned g_wfree[2];                      // gemm CTAs done with slot (32/step)

// ---- grid barrier ----
__device__ __forceinline__ void gbar(int idx, unsigned count) {
    __threadfence();
    __syncthreads();
    if (threadIdx.x == 0) {
        volatile unsigned* vg = (volatile unsigned*)&g_gen[idx];
        unsigned g = *vg;
        unsigned old = atomicAdd(&g_cnt[idx], 1u);
        if (old == count - 1) {
            g_cnt[idx] = 0;
            __threadfence();
            *vg = g + 1;
        } else {
            while (*vg == g) {}
            __threadfence();
        }
    }
    __syncthreads();
}

// ---- release/acquire flag protocol (R16-validated) ----
__device__ __forceinline__ void arrive(unsigned* f) {
    __syncthreads();
    if (threadIdx.x == 0)
        asm volatile("red.release.gpu.add.u32 [%0], 1;" :: "l"(f) : "memory");
}
__device__ __forceinline__ void waitflag(unsigned* f, unsigned target) {
    __syncthreads();
    if (threadIdx.x == 0) {
        unsigned v;
        do {
            asm volatile("ld.acquire.gpu.b32 %0, [%1];" : "=r"(v) : "l"(f) : "memory");
        } while (v < target);
    }
    __syncthreads();
}

// ---- helpers ----
__device__ __forceinline__ void cpa(void* dst, const void* src) {
    uint32_t d = (uint32_t)__cvta_generic_to_shared(dst);
    asm volatile("cp.async.cg.shared.global [%0], [%1], 16;" :: "r"(d), "l"(src));
}
#define CPCOMMIT() asm volatile("cp.async.commit_group;")
#define CPWAIT(n)  asm volatile("cp.async.wait_group %0;" :: "n"(n))

__device__ __forceinline__ void mma16h(float* c, uint32_t a0, uint32_t a1,
                                       uint32_t a2, uint32_t a3,
                                       uint32_t b0, uint32_t b1) {
    asm volatile(
        "mma.sync.aligned.m16n8k16.row.col.f32.f16.f16.f32 "
        "{%0,%1,%2,%3},{%4,%5,%6,%7},{%8,%9},{%0,%1,%2,%3};"
        : "+f"(c[0]), "+f"(c[1]), "+f"(c[2]), "+f"(c[3])
        : "r"(a0), "r"(a1), "r"(a2), "r"(a3), "r"(b0), "r"(b1));
}

// helper CTA: convert its row range of Wh[t] -> ring slot p
__device__ __forceinline__ void fill_ring(const float* __restrict__ Wh,
                                          int t, int p, int r0, int nr, int tid) {
    for (int e = tid; e < nr * 256; e += NTHREADS) {
        int n  = r0 + (e >> 8);
        int w4 = e & 255;
        float4 f = __ldcg((const float4*)(Wh + ((size_t)t * HH + n) * HH + w4 * 4));
        __half2 h0 = __floats2half2_rn(f.x, f.y);
        __half2 h1 = __floats2half2_rn(f.z, f.w);
        uint2 o;
        o.x = *(unsigned*)&h0;
        o.y = *(unsigned*)&h1;
        *(uint2*)(&g_w16ring[p][(size_t)n * HH + w4 * 4]) = o;
    }
}

// ---- persistent kernel ----
__global__ void __launch_bounds__(NTHREADS, 1)
SequenceModelPadded_kernel(
    const float* __restrict__ inp,        // (B,T,I)
    const void*  __restrict__ slen_raw,   // (B,) int64 OR int32
    const float* __restrict__ Wx,         // (T,H,I)
    const float* __restrict__ Wh,         // (T,H,H)
    const float* __restrict__ bias,       // (T,H)
    const float* __restrict__ Wout,       // (1,H)
    const float* __restrict__ bout,       // (1,)
    float* __restrict__ out)              // (B,1)
{
    extern __shared__ float sm[];
    __shared__ int s_is64;
    __shared__ int s_perm[256];
    __shared__ int s_lorig[256];
    __shared__ int s_lsorted[256];
    __shared__ int s_act[256];

    int tid  = threadIdx.x;
    int bx   = blockIdx.x;

    int lane = tid & 31, warp = tid >> 5;
    int g  = lane >> 2, tg = lane & 3;

    // ---- seq_lengths dtype sniff ----
    if (tid == 0) {
        const unsigned* w = (const unsigned*)slen_raw;
        unsigned z = 0;
        for (int i = 1; i < 256; i += 2) z |= __ldg(&w[i]);
        s_is64 = (z == 0) ? 1 : 0;
    }
    __syncthreads();
    const int is64 = s_is64;

    // ---- stable sort of lengths (descending) ----
    {
        int L = is64 ? (int)__ldg(&((const int*)slen_raw)[tid * 2])
                     : (int)__ldg(&((const int*)slen_raw)[tid]);
        s_lorig[tid] = L;
        __syncthreads();
        int rank = 0;
        for (int j = 0; j < 256; j++) {
            int Lj = s_lorig[j];
            rank += (Lj > L) || (Lj == L && j < tid);
        }
        s_perm[rank]    = tid;
        s_lsorted[rank] = L;
        __syncthreads();
        int h2 = (bx >> 4) & 1;   // gemm half (garbage for helpers, unused)
        int a = 0;
        for (int rl = 0; rl < 128; rl++)
            a += (s_lsorted[2 * rl + h2] > tid) ? 1 : 0;
        s_act[tid] = a;
        __syncthreads();
    }
    const int tmaxAll = s_lsorted[0];

    // ---- zero BOTH h buffers ----
    for (int e = tid; e < 1024; e += NTHREADS) {
        ((unsigned*)&g_h[0][0])[bx * 1024 + e] = 0u;
        ((unsigned*)&g_h[1][0])[bx * 1024 + e] = 0u;
    }

    // ---- reset flags, publish before anyone arrives ----
    if (bx == 0 && tid == 0) {
        g_hflag[0] = 0; g_hflag[1] = 0;
        g_wready[0] = 0; g_wready[1] = 0;
        g_wfree[0] = 0; g_wfree[1] = 0;
    }
    gbar(0, NCTA);

    // ============================================================
    // PROLOGUE (fp16 mma, R16-validated): xpart[t, ss(r)] = x @ Wx[t]^T
    // ============================================================
    {
        int wmP = warp & 3, wnP = warp >> 2;   // 4 x 2
        for (int rep = 0; rep < 2; rep++) {
            int t = bx + rep * 128;
            int actp = 0;
            for (int j = 0; j < 256; j++) actp += (s_lsorted[j] > t) ? 1 : 0;
            if (actp == 0) continue;
            int actpL = (actp + 15) & ~15;

            for (int nt = 0; nt < 8; nt++) {
                float acc[4][8][4];
#pragma unroll
                for (int s = 0; s < 4; s++)
#pragma unroll
                    for (int u = 0; u < 8; u++)
#pragma unroll
                        for (int q = 0; q < 4; q++) acc[s][u][q] = 0.f;

                {   // chunk 0 fp32 loads
                    float* pa = sm + P_A32;
                    float* pw = sm + P_W32;
#pragma unroll
                    for (int it = 0; it < 8; it++) {
                        int v = tid + NTHREADS * it; int row = v >> 3, seg = v & 7;
                        if (row < actpL) {
                            int pr = s_perm[row];
                            cpa(pa + row * 36 + seg * 4,
                                inp + (size_t)pr * (TT * II) + (size_t)t * II + seg * 4);
                        }
                    }
#pragma unroll
                    for (int it = 0; it < 4; it++) {
                        int v = tid + NTHREADS * it; int row = v >> 3, seg = v & 7;
                        cpa(pw + row * 36 + seg * 4,
                            Wx + ((size_t)t * HH + nt * 128 + row) * II + seg * 4);
                    }
                    CPCOMMIT();
                }
                for (int ch = 0; ch < 16; ch++) {
                    if (ch < 15) {
                        int nb = (ch + 1) & 1;
                        float* pa = sm + P_A32 + nb * P_A32_BUF;
                        float* pw = sm + P_W32 + nb * P_W32_BUF;
                        int ko = (ch + 1) * 32;
#pragma unroll
                        for (int it = 0; it < 8; it++) {
                            int v = tid + NTHREADS * it; int row = v >> 3, seg = v & 7;
                            if (row < actpL) {
                                int pr = s_perm[row];
                                cpa(pa + row * 36 + seg * 4,
                                    inp + (size_t)pr * (TT * II) + (size_t)t * II + ko + seg * 4);
                            }
                        }
#pragma unroll
                        for (int it = 0; it < 4; it++) {
                            int v = tid + NTHREADS * it; int row = v >> 3, seg = v & 7;
                            cpa(pw + row * 36 + seg * 4,
                                Wx + ((size_t)t * HH + nt * 128 + row) * II + ko + seg * 4);
                        }
                        CPCOMMIT();
                        CPWAIT(1);
                    } else {
                        CPWAIT(0);
                    }
                    __syncthreads();

                    {   // cvt fp32 chunk -> fp16 tiles
                        const float* pa = sm + P_A32 + (ch & 1) * P_A32_BUF;
                        const float* pw = sm + P_W32 + (ch & 1) * P_W32_BUF;
                        unsigned short* pa16 = (unsigned short*)(sm + P_A16);
                        unsigned short* pw16 = (unsigned short*)(sm + P_W16);
#pragma unroll
                        for (int it = 0; it < 8; it++) {
                            int v = tid + NTHREADS * it;
                            int row = v >> 3, seg = v & 7;
                            float4 f = *(const float4*)(pa + row * 36 + seg * 4);
                            __half2 h0 = __floats2half2_rn(f.x, f.y);
                            __half2 h1 = __floats2half2_rn(f.z, f.w);
                            uint2 o; o.x = *(unsigned*)&h0; o.y = *(unsigned*)&h1;
                            *(uint2*)(pa16 + row * 40 + seg * 4) = o;
                        }
#pragma unroll
                        for (int it = 0; it < 4; it++) {
                            int v = tid + NTHREADS * it;
                            int row = v >> 3, seg = v & 7;
                            float4 f = *(const float4*)(pw + row * 36 + seg * 4);
                            __half2 h0 = __floats2half2_rn(f.x, f.y);
                            __half2 h1 = __floats2half2_rn(f.z, f.w);
                            uint2 o; o.x = *(unsigned*)&h0; o.y = *(unsigned*)&h1;
                            *(uint2*)(pw16 + row * 40 + seg * 4) = o;
                        }
                    }
                    __syncthreads();

                    {   // fp16 mma over the 32-wide chunk
                        const unsigned short* pa16 = (const unsigned short*)(sm + P_A16);
                        const unsigned short* pw16 = (const unsigned short*)(sm + P_W16);
#pragma unroll
                        for (int kk = 0; kk < 2; kk++) {
                            uint32_t ua[4][4];
#pragma unroll
                            for (int s = 0; s < 4; s++) {
                                if (wmP * 64 + s * 16 < actp) {
                                    int base = (wmP * 64 + s * 16 + g) * 40 + kk * 16 + 2 * tg;
                                    ua[s][0] = *(const unsigned*)(pa16 + base);
                                    ua[s][1] = *(const unsigned*)(pa16 + base + 8 * 40);
                                    ua[s][2] = *(const unsigned*)(pa16 + base + 8);
                                    ua[s][3] = *(const unsigned*)(pa16 + base + 8 * 40 + 8);
                                }
                            }
#pragma unroll
                            for (int u = 0; u < 8; u++) {
                                int wb = (wnP * 64 + u * 8 + g) * 40 + kk * 16 + 2 * tg;
                                uint32_t b0 = *(const unsigned*)(pw16 + wb);
                                uint32_t b1 = *(const unsigned*)(pw16 + wb + 8);
#pragma unroll
                                for (int s = 0; s < 4; s++)
                                    if (wmP * 64 + s * 16 < actp)
                                        mma16h(acc[s][u], ua[s][0], ua[s][1], ua[s][2], ua[s][3], b0, b1);
                            }
                        }
                    }
                    __syncthreads();
                }
#pragma unroll
                for (int s = 0; s < 4; s++) {
                    if (wmP * 64 + s * 16 >= actp) continue;
#pragma unroll
                    for (int u = 0; u < 8; u++) {
                        int r0 = wmP * 64 + s * 16 + g;
                        int r1 = r0 + 8;
                        int c  = nt * 128 + wnP * 64 + u * 8 + 2 * tg;
                        int ss0 = ((r0 & 1) << 7) | (r0 >> 1);
                        int ss1 = ((r1 & 1) << 7) | (r1 >> 1);
                        *(float2*)(g_xpart + ((size_t)t * BB + ss0) * HH + c) =
                            make_float2(acc[s][u][0], acc[s][u][1]);
                        *(float2*)(g_xpart + ((size_t)t * BB + ss1) * HH + c) =
                            make_float2(acc[s][u][2], acc[s][u][3]);
                    }
                }
            }
        }
    }

    // ---- helper prefill of ring slots for t=0,1 ----
    int hid = bx - 32;
    int hr0 = 0, hnr = 0;
    if (bx >= 32) {
        hr0 = hid * 10 + (hid < 64 ? hid : 64);
        hnr = (hid < 64) ? 11 : 10;
        fill_ring(Wh, 0, 0, hr0, hnr, tid);
        arrive(&g_wready[0]);
        fill_ring(Wh, 1, 1, hr0, hnr, tid);
        arrive(&g_wready[1]);
    }

    gbar(2, NCTA);   // xpart + prefills + h-init + resets visible

    // ============================================================
    // LOOP
    // ============================================================
    if (bx < 32) {
        // -------- GEMM CTA: half = bx>>4, nblk = bx&15, N=64, K=1024 --------
        int half = bx >> 4;
        int nblk = bx & 15;
        int wm = warp & 1, wn = warp >> 1;   // 2(M) x 4(N)
        const int hmax = s_lsorted[half];

        for (int t = 0; t < hmax; t++) {
            int cur = t & 1;
            int nxt = cur ^ 1;
            int p   = t & 1;
            int act      = s_act[t];
            int act_prev = (t == 0) ? 128 : s_act[t - 1];
            int actL = (act + 15) & ~15;

            // combined wait: ring slot filled + h(t) ready
            __syncthreads();
            if (tid == 0) {
                unsigned v;
                unsigned wt = 96u * ((unsigned)(t >> 1) + 1u);
                do { asm volatile("ld.acquire.gpu.b32 %0, [%1];"
                                  : "=r"(v) : "l"(&g_wready[p]) : "memory"); } while (v < wt);
                unsigned ht = 16u * (unsigned)t;
                do { asm volatile("ld.acquire.gpu.b32 %0, [%1];"
                                  : "=r"(v) : "l"(&g_hflag[half]) : "memory"); } while (v < ht);
            }
            __syncthreads();

            const __half* hbuf = g_h[cur];
            const __half* wr   = g_w16ring[p];

            float acc[4][2][4];
#pragma unroll
            for (int s = 0; s < 4; s++)
#pragma unroll
                for (int u = 0; u < 2; u++)
#pragma unroll
                    for (int q = 0; q < 4; q++) acc[s][u][q] = 0.f;

            // pre-issue chunks 0,1
#pragma unroll
            for (int c0 = 0; c0 < 2; c0++) {
                __half* pa = (__half*)(sm + L_A + c0 * L_A_BUF);
                __half* pw = (__half*)(sm + L_W + c0 * L_W_BUF);
                int ko = c0 * 128;
#pragma unroll
                for (int it = 0; it < 8; it++) {
                    int v = tid + NTHREADS * it; int row = v >> 4, seg = v & 15;
                    if (row < actL)
                        cpa(pa + row * 136 + seg * 8,
                            hbuf + (size_t)(half * 128 + row) * HH + ko + seg * 8);
                }
#pragma unroll
                for (int it = 0; it < 4; it++) {
                    int v = tid + NTHREADS * it; int row = v >> 4, seg = v & 15;
                    cpa(pw + row * 136 + seg * 8,
                        wr + (size_t)(nblk * 64 + row) * HH + ko + seg * 8);
                }
                CPCOMMIT();
            }

            for (int ch = 0; ch < 8; ch++) {
                if (ch < 7) CPWAIT(1); else CPWAIT(0);
                __syncthreads();
                if (ch < 6) {   // issue chunk ch+2 into buf (ch+2)%3
                    int b = (ch + 2) % 3;
                    __half* pa = (__half*)(sm + L_A + b * L_A_BUF);
                    __half* pw = (__half*)(sm + L_W + b * L_W_BUF);
                    int ko = (ch + 2) * 128;
#pragma unroll
                    for (int it = 0; it < 8; it++) {
                        int v = tid + NTHREADS * it; int row = v >> 4, seg = v & 15;
                        if (row < actL)
                            cpa(pa + row * 136 + seg * 8,
                                hbuf + (size_t)(half * 128 + row) * HH + ko + seg * 8);
                    }
#pragma unroll
                    for (int it = 0; it < 4; it++) {
                        int v = tid + NTHREADS * it; int row = v >> 4, seg = v & 15;
                        cpa(pw + row * 136 + seg * 8,
                            wr + (size_t)(nblk * 64 + row) * HH + ko + seg * 8);
                    }
                    CPCOMMIT();
                }
                // compute chunk ch from buf ch%3
                const unsigned short* pa = (const unsigned short*)(sm + L_A + (ch % 3) * L_A_BUF);
                const unsigned short* pw = (const unsigned short*)(sm + L_W + (ch % 3) * L_W_BUF);
#pragma unroll
                for (int kk = 0; kk < 8; kk++) {
                    uint32_t ua[4][4];
#pragma unroll
                    for (int s = 0; s < 4; s++) {
                        if (wm * 64 + s * 16 < act) {
                            int base = (wm * 64 + s * 16 + g) * 136 + kk * 16 + 2 * tg;
                            ua[s][0] = *(const unsigned*)(pa + base);
                            ua[s][1] = *(const unsigned*)(pa + base + 8 * 136);
                            ua[s][2] = *(const unsigned*)(pa + base + 8);
                            ua[s][3] = *(const unsigned*)(pa + base + 8 * 136 + 8);
                        }
                    }
#pragma unroll
                    for (int u = 0; u < 2; u++) {
                        int wb = (wn * 16 + u * 8 + g) * 136 + kk * 16 + 2 * tg;
                        uint32_t b0 = *(const unsigned*)(pw + wb);
                        uint32_t b1 = *(const unsigned*)(pw + wb + 8);
#pragma unroll
                        for (int s = 0; s < 4; s++)
                            if (wm * 64 + s * 16 < act)
                                mma16h(acc[s][u], ua[s][0], ua[s][1], ua[s][2], ua[s][3], b0, b1);
                    }
                }
            }

            // epilogue: + xpart + bias -> tanh -> fp16 h[nxt], on fragments
#pragma unroll
            for (int s = 0; s < 4; s++) {
                int r0 = wm * 64 + s * 16 + g;
#pragma unroll
                for (int u = 0; u < 2; u++) {
                    int c = nblk * 64 + wn * 16 + u * 8 + 2 * tg;
                    float b0 = __ldg(&bias[(size_t)t * HH + c]);
                    float b1 = __ldg(&bias[(size_t)t * HH + c + 1]);
                    if (r0 < act) {
                        float2 xp = __ldcg((const float2*)&g_xpart[
                            ((size_t)t * BB + half * 128 + r0) * HH + c]);
                        __half2 hv = __floats2half2_rn(
                            tanhf(acc[s][u][0] + xp.x + b0),
                            tanhf(acc[s][u][1] + xp.y + b1));
                        *(unsigned*)&g_h[nxt][(size_t)(half * 128 + r0) * HH + c] =
                            *(unsigned*)&hv;
                    }
                    int r1 = r0 + 8;
                    if (r1 < act) {
                        float2 xp = __ldcg((const float2*)&g_xpart[
                            ((size_t)t * BB + half * 128 + r1) * HH + c]);
                        __half2 hv = __floats2half2_rn(
                            tanhf(acc[s][u][2] + xp.x + b0),
                            tanhf(acc[s][u][3] + xp.y + b1));
                        *(unsigned*)&g_h[nxt][(size_t)(half * 128 + r1) * HH + c] =
                            *(unsigned*)&hv;
                    }
                }
            }
            // frozen rows [act, act_prev): copy my 64 cols across buffers
            {
                int nfr = act_prev - act;
                for (int e = tid; e < nfr * 32; e += NTHREADS) {
                    int rr = act + (e >> 5), w = e & 31;
                    size_t base = (size_t)(half * 128 + rr) * HH + nblk * 64;
                    ((unsigned*)&g_h[nxt][base])[w] =
                        __ldcg(&((const unsigned*)&g_h[cur][base])[w]);
                }
            }

            // arrive: slot consumed + h(t+1) cols ready
            __syncthreads();
            if (tid == 0) {
                asm volatile("red.release.gpu.add.u32 [%0], 1;" :: "l"(&g_wfree[p]) : "memory");
                asm volatile("red.release.gpu.add.u32 [%0], 1;" :: "l"(&g_hflag[half]) : "memory");
            }
        }
        // drain wfree so helpers (and the other half) never stall on us
        __syncthreads();
        if (tid == 0)
            for (int td = hmax; td < tmaxAll; td++)
                asm volatile("red.release.gpu.add.u32 [%0], 1;" :: "l"(&g_wfree[td & 1]) : "memory");
    } else {
        // -------- helper CTA: keep the ring one step ahead --------
        for (int t = 2; t < tmaxAll; t++) {
            waitflag(&g_wfree[t & 1], 32u * (unsigned)(t >> 1));
            fill_ring(Wh, t, t & 1, hr0, hnr, tid);
            arrive(&g_wready[t & 1]);
        }
    }

    gbar(1, NCTA);   // all h writes globally visible

    // ---- output: out[perm[2*rl+halfo]] = h . Wout + bout (R16 epilogue) ----
    {
        int halfo = bx >> 6, lho = bx & 63;
        int hmaxo = s_lsorted[halfo];
        const __half* hfin = g_h[hmaxo & 1];
        float* red = sm;
#pragma unroll
        for (int rr = 0; rr < 2; rr++) {
            int rl = lho * 2 + rr;
            int gr = halfo * 128 + rl;
            int ob = s_perm[2 * rl + halfo];
            float pacc = 0.f;
            for (int c2 = tid * 2; c2 < HH; c2 += NTHREADS * 2) {
                unsigned uv = __ldcg((const unsigned*)(hfin + (size_t)gr * HH + c2));
                __half2 hv = *reinterpret_cast<__half2*>(&uv);
                pacc += __low2float(hv)  * __ldg(&Wout[c2]);
                pacc += __high2float(hv) * __ldg(&Wout[c2 + 1]);
            }
            red[tid] = pacc;
            __syncthreads();
            for (int s = 128; s > 0; s >>= 1) {
                if (tid < s) red[tid] += red[tid + s];
                __syncthreads();
            }
            if (tid == 0) out[ob] = red[0] + __ldg(&bout[0]);
            __syncthreads();
        }
    }
}

extern "C" void kernel_launch(void* const* d_in, const int* in_sizes, int n_in,
                              void* d_out, int out_size) {
    (void)in_sizes; (void)n_in; (void)out_size;
    const float* inp  = (const float*)d_in[0];
    const void*  slen = (const void*)d_in[1];
    const float* Wx   = (const float*)d_in[2];
    const float* Wh   = (const float*)d_in[3];
    const float* bias = (const float*)d_in[4];
    const float* Wout = (const float*)d_in[5];
    const float* bout = (const float*)d_in[6];
    float*       out  = (float*)d_out;

    static int s_attr_done = 0;
    if (!s_attr_done) {
        cudaFuncSetAttribute(SequenceModelPadded_kernel,
                             cudaFuncAttributeMaxDynamicSharedMemorySize, SMEM_BYTES);
        s_attr_done = 1;
    }
    SequenceModelPadded_kernel<<<NCTA, NTHREADS, SMEM_BYTES>>>(
        inp, slen, Wx, Wh, bias, Wout, bout, out);
}